// round 15
// baseline (speedup 1.0000x reference)
#include <cuda_runtime.h>
#include <cuda_fp16.h>
#include <math.h>
#include <stdint.h>

#define SQ   2048
#define DM   768
#define NH   12
#define HD   64
#define NE   8
#define NI   1024
#define ISH  2048
#define NSLOT (2*SQ)

// ---------------- device scratch ----------------
__device__ __align__(16) __half g_xn[SQ*DM];
__device__ __align__(16) float g_res[SQ*DM];
__device__ __align__(16) __half g_xf[SQ*DM];
__device__ __align__(16) __half g_t [SQ*ISH];
__device__ __align__(16) __half g_a [NSLOT*NI];
__device__ __align__(16) __half g_gv[NSLOT*NI];
__device__ __align__(16) __half g_h [NSLOT*NI];
__device__ __align__(16) __half g_yk[NSLOT*DM];
__device__ float g_logits[SQ*NE];
__device__ float g_wts[NSLOT];
__device__ int   g_counts[NE];
__device__ int   g_offsets[NE];
__device__ int   g_list[NSLOT];
__device__ __align__(16) __half h_w1 [NE*NI*DM];
__device__ __align__(16) __half h_w3 [NE*NI*DM];
__device__ __align__(16) __half h_w2 [NE*DM*NI];
__device__ __align__(16) __half h_fc1[ISH*DM];
__device__ __align__(16) __half h_fc2[DM*ISH];

// ---------------- helpers ----------------
__device__ __forceinline__ uint32_t smem_u32(const void* p){
    uint32_t a;
    asm("{ .reg .u64 t; cvta.to.shared.u64 t, %1; cvt.u32.u64 %0, t; }" : "=r"(a) : "l"(p));
    return a;
}
__device__ __forceinline__ void mma16(float* d, const uint32_t* a, const uint32_t* b){
    asm volatile("mma.sync.aligned.m16n8k16.row.col.f32.f16.f16.f32 "
        "{%0,%1,%2,%3}, {%4,%5,%6,%7}, {%8,%9}, {%0,%1,%2,%3};"
        : "+f"(d[0]), "+f"(d[1]), "+f"(d[2]), "+f"(d[3])
        : "r"(a[0]), "r"(a[1]), "r"(a[2]), "r"(a[3]), "r"(b[0]), "r"(b[1]));
}
__device__ __forceinline__ void ldm4(uint32_t* r, uint32_t addr){
    asm volatile("ldmatrix.sync.aligned.m8n8.x4.shared.b16 {%0,%1,%2,%3}, [%4];"
        : "=r"(r[0]), "=r"(r[1]), "=r"(r[2]), "=r"(r[3]) : "r"(addr));
}
__device__ __forceinline__ void cpasync16(uint32_t dst, const void* src){
    asm volatile("cp.async.cg.shared.global [%0], [%1], 16;" :: "r"(dst), "l"(src) : "memory");
}
#define CP_COMMIT() asm volatile("cp.async.commit_group;" ::: "memory")

__device__ __forceinline__ float fexp2n(float y){
    y = fminf(fmaxf(y, -126.f), 126.f);
    float r = y + 12582912.f;
    float f = y - (r - 12582912.f);
    float p = 1.3333558146e-3f;
    p = fmaf(p, f, 9.6181291776e-3f);
    p = fmaf(p, f, 5.5504108664e-2f);
    p = fmaf(p, f, 2.4022650696e-1f);
    p = fmaf(p, f, 6.9314718056e-1f);
    p = fmaf(p, f, 1.0f);
    return __int_as_float(__float_as_int(p) + (__float_as_int(r) << 23));
}
__device__ __forceinline__ float fexps17(float s){
    return fexp2n(fmaf(s, 0.18033688011112042f, -17.0f));
}
__device__ __forceinline__ float frcp(float x){
    float y = __int_as_float(0x7EF311C3 - __float_as_int(x));
    y = y * (2.f - x*y);
    y = y * (2.f - x*y);
    y = y * (2.f - x*y);
    return y;
}
__device__ __forceinline__ float fsilu(float a){
    float t = fexp2n(-a * 1.4426950408889634f);
    return a * frcp(1.f + t);
}

// ---------------- fp32 -> fp16 conversion ----------------
__global__ void __launch_bounds__(256) cvt_kernel(const float4* __restrict__ src,
                                                  __half2* __restrict__ dst, int n4)
{
    int i = blockIdx.x * 256 + threadIdx.x;
    if (i < n4) {
        float4 v = src[i];
        dst[2*i]   = __floats2half2_rn(v.x, v.y);
        dst[2*i+1] = __floats2half2_rn(v.z, v.w);
    }
}

// ---------------- rmsnorm ----------------
template<int WHICH>
__global__ void __launch_bounds__(256) rmsnorm_kernel(const float* __restrict__ x,
                                                      const float* __restrict__ w,
                                                      const float* __restrict__ gw)
{
    int n = blockIdx.x;
    int t = threadIdx.x;
    const float* row = (WHICH == 0) ? (x + (size_t)n*DM) : (g_res + (size_t)n*DM);

    float v0 = row[t], v1 = row[t+256], v2 = row[t+512];
    float ss = v0*v0 + v1*v1 + v2*v2;

    __shared__ float red[8];
    __shared__ float part[8][8];
    #pragma unroll
    for (int o = 16; o; o >>= 1) ss += __shfl_down_sync(0xffffffffu, ss, o);
    if ((t & 31) == 0) red[t >> 5] = ss;
    __syncthreads();
    if (t < 8) {
        ss = red[t];
        #pragma unroll
        for (int o = 4; o; o >>= 1) ss += __shfl_down_sync(0xffu, ss, o);
        if (t == 0) red[0] = ss;
    }
    __syncthreads();
    float inv = rsqrtf(red[0] * (1.0f/DM) + 1e-5f);
    float o0 = v0*inv*w[t], o1 = v1*inv*w[t+256], o2 = v2*inv*w[t+512];
    __half* out = (WHICH == 0) ? (g_xn + (size_t)n*DM) : (g_xf + (size_t)n*DM);
    out[t]     = __float2half_rn(o0);
    out[t+256] = __float2half_rn(o1);
    out[t+512] = __float2half_rn(o2);

    if (WHICH == 1) {
        float d[8];
        #pragma unroll
        for (int e = 0; e < 8; e++)
            d[e] = o0*gw[e*DM + t] + o1*gw[e*DM + t + 256] + o2*gw[e*DM + t + 512];
        #pragma unroll
        for (int e = 0; e < 8; e++) {
            #pragma unroll
            for (int o = 16; o; o >>= 1) d[e] += __shfl_down_sync(0xffffffffu, d[e], o);
        }
        if ((t & 31) == 0) {
            #pragma unroll
            for (int e = 0; e < 8; e++) part[t >> 5][e] = d[e];
        }
        __syncthreads();
        if (t < 8) {
            float l = 0.f;
            #pragma unroll
            for (int wv = 0; wv < 8; wv++) l += part[wv][t];
            g_logits[n*NE + t] = l;
        }
    }
}

// ---------------- merged routing ----------------
__global__ void __launch_bounds__(1024) route_kernel()
{
    __shared__ int cnt[NE], off[NE], fill[NE];
    int t = threadIdx.x;
    if (t < NE) { cnt[t] = 0; fill[t] = 0; }
    __syncthreads();

    int eidx[2][2];
    #pragma unroll
    for (int j = 0; j < 2; j++) {
        int n = t*2 + j;
        float lg[NE];
        #pragma unroll
        for (int i = 0; i < NE; i++) lg[i] = g_logits[n*NE + i];
        float m = -1e30f;
        #pragma unroll
        for (int i = 0; i < NE; i++) m = fmaxf(m, lg[i]);
        float s = 0.f;
        #pragma unroll
        for (int i = 0; i < NE; i++) { lg[i] = fexp2n((lg[i] - m) * 1.4426950408889634f); s += lg[i]; }
        float invs = 1.f / s;
        int e0 = -1, e1 = -1; float v0 = -1.f, v1 = -1.f;
        #pragma unroll
        for (int i = 0; i < NE; i++) {
            float v = lg[i] * invs;
            if (v > v0) { v1 = v0; e1 = e0; v0 = v; e0 = i; }
            else if (v > v1) { v1 = v; e1 = i; }
        }
        g_wts[2*n]     = fmaxf(v0, 1e-7f);
        g_wts[2*n + 1] = fmaxf(v1, 1e-7f);
        eidx[j][0] = e0; eidx[j][1] = e1;
        atomicAdd(&cnt[e0], 1);
        atomicAdd(&cnt[e1], 1);
    }
    __syncthreads();
    if (t == 0) {
        int o = 0;
        for (int e = 0; e < NE; e++) { g_counts[e] = cnt[e]; off[e] = o; g_offsets[e] = o; o += cnt[e]; }
    }
    __syncthreads();
    #pragma unroll
    for (int j = 0; j < 2; j++) {
        #pragma unroll
        for (int k = 0; k < 2; k++) {
            int e = eidx[j][k];
            int p = atomicAdd(&fill[e], 1);
            g_list[off[e] + p] = (t*2 + j)*2 + k;
        }
    }
}

// ---------------- attention: all-fp16 mma + ldmatrix + scaled fast exp ----------------
__global__ void __launch_bounds__(256) attn_mma_kernel(const float* __restrict__ x)
{
    int q0 = blockIdx.x * 64;
    int h  = blockIdx.y;

    extern __shared__ __align__(16) uint32_t sm[];
    uint32_t* Qs = sm;
    uint32_t* Ks = sm + 2048;
    uint32_t* Vt = sm + 4096;
    uint32_t* Ps = sm + 6144;
    float* rssm  = (float*)(sm + 8192);

    int tid = threadIdx.x, lane = tid & 31, wid = tid >> 5;
    int wm = wid & 3, wn = wid >> 2, gid = lane >> 2, qid = lane & 3;

    uint32_t qBase = smem_u32(Qs), kBase = smem_u32(Ks);
    uint32_t vBase = smem_u32(Vt), pBase = smem_u32(Ps);

    int aRow = wm*16 + (lane & 15);
    uint32_t aHalf = (uint32_t)(lane >> 4) * 16u;
    uint32_t aXor  = (uint32_t)((aRow & 7) << 4);
    uint32_t aTerm = (uint32_t)(aRow * 128);
    int bRow = wn*32 + ((lane >> 4) << 3) + (lane & 7);
    uint32_t bHalf = (uint32_t)((lane >> 3) & 1) * 16u;
    uint32_t bXor  = (uint32_t)((bRow & 7) << 4);
    uint32_t bTerm0 = (uint32_t)(bRow * 128);
    uint32_t bTerm1 = (uint32_t)((bRow + 16) * 128);

    {
        int r = tid >> 2, b0 = (tid & 3) * 32;
        const __half* src = g_xn + (size_t)(q0 + r)*DM + h*HD + b0/2;
        char* qb = (char*)Qs;
        *(uint4*)(qb + r*128 + ((b0      ) ^ ((r & 7) << 4))) = *(const uint4*)src;
        *(uint4*)(qb + r*128 + ((b0 + 16) ^ ((r & 7) << 4))) = *(const uint4*)(src + 8);
    }

    float acc_o[4][4] = {};
    float rs0 = 0.f, rs1 = 0.f;
    int r0 = wm*16 + gid;

    for (int kt = 0; kt < SQ/64; kt++) {
        __syncthreads();
        {
            int r = tid >> 2, b0 = (tid & 3) * 32;
            const __half* src = g_xn + (size_t)(kt*64 + r)*DM + h*HD + b0/2;
            uint4 u0 = *(const uint4*)src;
            uint4 u1 = *(const uint4*)(src + 8);
            char* kb = (char*)Ks;
            *(uint4*)(kb + r*128 + ((b0      ) ^ ((r & 7) << 4))) = u0;
            *(uint4*)(kb + r*128 + ((b0 + 16) ^ ((r & 7) << 4))) = u1;

            uint32_t w[8] = {u0.x,u0.y,u0.z,u0.w,u1.x,u1.y,u1.z,u1.w};
            uint32_t pw[8];
            #pragma unroll
            for (int j = 0; j < 8; j++) pw[j] = __shfl_xor_sync(0xffffffffu, w[j], 4);
            if ((r & 1) == 0) {
                const __half* mh = (const __half*)w;
                const __half* ph = (const __half*)pw;
                int wt = r >> 1;
                int d0 = b0 >> 1;
                #pragma unroll
                for (int d = 0; d < 16; d++) {
                    uint32_t val = ((uint32_t)__half_as_ushort(ph[d]) << 16)
                                 |  (uint32_t)__half_as_ushort(mh[d]);
                    int dd = d0 + d;
                    Vt[dd*32 + (wt ^ ((dd & 7) << 2))] = val;
                }
            }
        }
        __syncthreads();

        float acc_s[4][4] = {};
        #pragma unroll
        for (int kk = 0; kk < 4; kk++) {
            uint32_t kbyte = (uint32_t)(kk * 32);
            uint32_t aoff = (kbyte + aHalf) ^ aXor;
            uint32_t boff = (kbyte + bHalf) ^ bXor;
            uint32_t af[4], b0f[4], b1f[4];
            ldm4(af,  qBase + aTerm + aoff);
            ldm4(b0f, kBase + bTerm0 + boff);
            ldm4(b1f, kBase + bTerm1 + boff);
            mma16(acc_s[0], af, b0f);
            mma16(acc_s[1], af, b0f + 2);
            mma16(acc_s[2], af, b1f);
            mma16(acc_s[3], af, b1f + 2);
        }

        float p0 = 0.f, p1 = 0.f;
        #pragma unroll
        for (int ni = 0; ni < 4; ni++) {
            float e0 = fexps17(acc_s[ni][0]);
            float e1 = fexps17(acc_s[ni][1]);
            float e2 = fexps17(acc_s[ni][2]);
            float e3 = fexps17(acc_s[ni][3]);
            p0 += e0 + e1;
            p1 += e2 + e3;
            int cw = (wn*32 + 8*ni + 2*qid) >> 1;
            __half2 h01 = __floats2half2_rn(e0, e1);
            __half2 h23 = __floats2half2_rn(e2, e3);
            Ps[r0*32 + (cw ^ ((r0 & 7) << 2))] = *(uint32_t*)&h01;
            int r1 = r0 + 8;
            Ps[r1*32 + (cw ^ ((r1 & 7) << 2))] = *(uint32_t*)&h23;
        }
        p0 += __shfl_xor_sync(0xffffffffu, p0, 1);
        p0 += __shfl_xor_sync(0xffffffffu, p0, 2);
        p1 += __shfl_xor_sync(0xffffffffu, p1, 1);
        p1 += __shfl_xor_sync(0xffffffffu, p1, 2);
        rs0 += p0; rs1 += p1;
        __syncthreads();

        #pragma unroll
        for (int kk = 0; kk < 4; kk++) {
            uint32_t kbyte = (uint32_t)(kk * 32);
            uint32_t aoff = (kbyte + aHalf) ^ aXor;
            uint32_t boff = (kbyte + bHalf) ^ bXor;
            uint32_t af[4], b0f[4], b1f[4];
            ldm4(af,  pBase + aTerm + aoff);
            ldm4(b0f, vBase + bTerm0 + boff);
            ldm4(b1f, vBase + bTerm1 + boff);
            mma16(acc_o[0], af, b0f);
            mma16(acc_o[1], af, b0f + 2);
            mma16(acc_o[2], af, b1f);
            mma16(acc_o[3], af, b1f + 2);
        }
    }

    if (qid == 0) {
        rssm[wn*64 + r0]     = rs0;
        rssm[wn*64 + r0 + 8] = rs1;
    }
    __syncthreads();
    float inv0 = 1.f / (rssm[r0]     + rssm[64 + r0]);
    float inv1 = 1.f / (rssm[r0 + 8] + rssm[64 + r0 + 8]);

    #pragma unroll
    for (int ni = 0; ni < 4; ni++) {
        int col = h*HD + wn*32 + 8*ni + 2*qid;
        size_t gi0 = (size_t)(q0 + r0)*DM + col;
        size_t gi1 = (size_t)(q0 + r0 + 8)*DM + col;
        float2 x0 = *(const float2*)&x[gi0];
        float2 x1 = *(const float2*)&x[gi1];
        float2 o0 = make_float2(x0.x + acc_o[ni][0]*inv0, x0.y + acc_o[ni][1]*inv0);
        float2 o1 = make_float2(x1.x + acc_o[ni][2]*inv1, x1.y + acc_o[ni][3]*inv1);
        *(float2*)&g_res[gi0] = o0;
        *(float2*)&g_res[gi1] = o1;
    }
}

// ---------------- h = silu(a) * g -> fp16 ----------------
__global__ void silu_mul_kernel()
{
    int i = (blockIdx.x * 256 + threadIdx.x) * 4;
    __half2 a01 = *(__half2*)&g_a[i],  a23 = *(__half2*)&g_a[i+2];
    __half2 g01 = *(__half2*)&g_gv[i], g23 = *(__half2*)&g_gv[i+2];
    float2 a0 = __half22float2(a01), a2 = __half22float2(a23);
    float2 g0 = __half22float2(g01), g2 = __half22float2(g23);
    *(__half2*)&g_h[i]   = __floats2half2_rn(fsilu(a0.x)*g0.x, fsilu(a0.y)*g0.y);
    *(__half2*)&g_h[i+2] = __floats2half2_rn(fsilu(a2.x)*g2.x, fsilu(a2.y)*g2.y);
}

// ---------------- fp16 mma GEMM, ldmatrix, BM x BN tiles ----------------
// MODE 0: fc1 : A=g_xf          B=h_fc1     -> g_t(fp16) silu(acc+bias)
// MODE 1: fc2 : A=g_t           B=h_fc2     -> out       acc+bias+res+yk0+yk1
// MODE 2: up  : A=g_xf (gather) B=h_w1/h_w3 -> g_a/g_gv  acc+bias (fp16)
// MODE 3: dn  : A=g_h (compact) B=h_w2      -> g_yk(fp16) wts*(acc+bias) scatter
template<int MODE, int BM, int BN>
__global__ void __launch_bounds__(256, 2) mma_gemm(const __half* __restrict__ Bw,
                                                   const __half* __restrict__ Bw2,
                                                   float* __restrict__ Cout,
                                                   const float* __restrict__ bias,
                                                   const float* __restrict__ bias2)
{
    constexpr int KD  = (MODE==1) ? ISH : (MODE==3 ? NI : DM);
    constexpr int NC  = KD / 64;
    constexpr int NN  = (MODE==0) ? ISH : (MODE==2 ? NI : DM);
    constexpr int AW  = BM * 32;                 // A stage words
    constexpr int BW  = BN * 32;                 // B stage words
    constexpr int BOFF = 3 * AW;                 // B stages start (words)
    constexpr int WMN = (BM==128) ? 4 : 2;       // warps along m
    constexpr int WNN = 8 / WMN;                 // warps along n
    constexpr int WNW = BN / WNN;                // warp n width
    constexpr int NIT = WNW / 8;                 // 8-wide n subtiles per warp
    // loader geometry
    constexpr int TPRA = 256 / BM;               // threads per A row
    constexpr int NCA  = 128 / TPRA / 16;        // cp16 per thread (A)
    constexpr int TPRB = 256 / BN;
    constexpr int NCB  = 128 / TPRB / 16;

    int bx = blockIdx.x;
    int tgt = 0;
    const __half* Bsel = Bw;
    const float* bsel = bias;
    if (MODE == 2 && bx >= NI/BN) { tgt = 1; bx -= NI/BN; Bsel = Bw2; bsel = bias2; }
    int n0 = bx * BN;
    int m0 = blockIdx.y * BM;
    int M = SQ, moff = 0;

    if (MODE >= 2) {
        int e = blockIdx.z;
        int cnt = g_counts[e];
        if (m0 >= cnt) return;
        M = cnt; moff = g_offsets[e];
        Bsel += (size_t)e * NN * KD;
        bsel += (size_t)e * NN;
    }

    extern __shared__ __align__(128) uint32_t smu[];
    uint32_t smbase = smem_u32(smu);

    int tid = threadIdx.x, lane = tid & 31, wid = tid >> 5;
    int wm = wid & (WMN-1), wn = wid / WMN;
    int gid = lane >> 2, qid = lane & 3;

    // A loader
    int ra = tid / TPRA;
    int ab0 = (tid % TPRA) * (128 / TPRA);
    int hofa[NCA]; uint32_t sba[NCA];
    #pragma unroll
    for (int i = 0; i < NCA; i++) {
        int bo = ab0 + i*16;
        hofa[i] = bo >> 1;
        sba[i] = (uint32_t)(ra*128 + (bo ^ ((ra & 7) << 4)));
    }
    int mrow = m0 + ra; if (mrow > M - 1) mrow = M - 1;
    const __half* arow;
    if      (MODE == 2) arow = g_xf + (size_t)(g_list[moff + mrow] >> 1) * DM;
    else if (MODE == 3) arow = g_h  + (size_t)(moff + mrow) * NI;
    else if (MODE == 1) arow = g_t  + (size_t)mrow * ISH;
    else                arow = g_xf + (size_t)mrow * DM;

    // B loader
    int rb = tid / TPRB;
    int bb0 = (tid % TPRB) * (128 / TPRB);
    const __half* brow = Bsel + (size_t)(n0 + rb) * KD;
    int hofb[NCB]; uint32_t sbb[NCB];
    #pragma unroll
    for (int i = 0; i < NCB; i++) {
        int bo = bb0 + i*16;
        hofb[i] = bo >> 1;
        sbb[i] = (uint32_t)(rb*128 + (bo ^ ((rb & 7) << 4)));
    }

    // ldmatrix addressing
    int aRow0 = 32*wm + (lane & 15);
    uint32_t aHalf = (uint32_t)(lane >> 4) * 16u;
    uint32_t aXor  = (uint32_t)((aRow0 & 7) << 4);
    uint32_t aTerm[2];
    aTerm[0] = (uint32_t)(aRow0 * 128);
    aTerm[1] = (uint32_t)((aRow0 + 16) * 128);
    int bRow0 = WNW*wn + ((lane >> 4) << 3) + (lane & 7);
    uint32_t bHalf = (uint32_t)((lane >> 3) & 1) * 16u;
    uint32_t bXor  = (uint32_t)((bRow0 & 7) << 4);
    uint32_t bTerm[NIT/2 > 0 ? NIT/2 : 1];
    #pragma unroll
    for (int j = 0; j < NIT/2; j++) bTerm[j] = (uint32_t)((bRow0 + 16*j) * 128);

#define ISSUE_CHUNK(KC) do { \
        int _kc = (KC); \
        int _st = _kc % 3; \
        uint32_t _da = smbase + (uint32_t)(_st * AW * 4); \
        uint32_t _db = smbase + (uint32_t)((BOFF + _st * BW) * 4); \
        const __half* _as = arow + _kc*64; \
        const __half* _bs = brow + _kc*64; \
        _Pragma("unroll") \
        for (int _i = 0; _i < NCA; _i++) cpasync16(_da + sba[_i], _as + hofa[_i]); \
        _Pragma("unroll") \
        for (int _i = 0; _i < NCB; _i++) cpasync16(_db + sbb[_i], _bs + hofb[_i]); \
        CP_COMMIT(); \
    } while (0)

    ISSUE_CHUNK(0);
    ISSUE_CHUNK(1);

    float acc[2][NIT][4] = {};

    for (int kc = 0; kc < NC; kc++) {
        if (kc == NC - 1) { asm volatile("cp.async.wait_group 0;" ::: "memory"); }
        else              { asm volatile("cp.async.wait_group 1;" ::: "memory"); }
        __syncthreads();
        if (kc + 2 < NC) ISSUE_CHUNK(kc + 2);

        int st = kc % 3;
        uint32_t aBase = smbase + (uint32_t)(st * AW * 4);
        uint32_t bBase = smbase + (uint32_t)((BOFF + st * BW) * 4);
        #pragma unroll
        for (int kk = 0; kk < 4; kk++) {
            uint32_t kbyte = (uint32_t)(kk * 32);
            uint32_t aoff = (kbyte + aHalf) ^ aXor;
            uint32_t boff = (kbyte + bHalf) ^ bXor;
            uint32_t af[2][4], bf[NIT][2];
            ldm4(af[0], aBase + aTerm[0] + aoff);
            ldm4(af[1], aBase + aTerm[1] + aoff);
            #pragma unroll
            for (int j = 0; j < NIT/2; j++) {
                uint32_t r4[4];
                ldm4(r4, bBase + bTerm[j] + boff);
                bf[2*j][0]   = r4[0]; bf[2*j][1]   = r4[1];
                bf[2*j+1][0] = r4[2]; bf[2*j+1][1] = r4[3];
            }
            #pragma unroll
            for (int mi = 0; mi < 2; mi++)
                #pragma unroll
                for (int ni = 0; ni < NIT; ni++)
                    mma16(acc[mi][ni], af[mi], bf[ni]);
        }
    }
#undef ISSUE_CHUNK

    #pragma unroll
    for (int mi = 0; mi < 2; mi++) {
        #pragma unroll
        for (int half = 0; half < 2; half++) {
            int row = m0 + 32*wm + 16*mi + gid + 8*half;
            if (MODE >= 2 && row >= M) continue;
            #pragma unroll
            for (int ni = 0; ni < NIT; ni++) {
                float v0 = acc[mi][ni][2*half + 0];
                float v1 = acc[mi][ni][2*half + 1];
                int col = n0 + WNW*wn + 8*ni + 2*qid;
                float b0 = bsel[col], b1 = bsel[col + 1];
                if (MODE == 0) {
                    *(__half2*)&g_t[(size_t)row*ISH + col] =
                        __floats2half2_rn(fsilu(v0 + b0), fsilu(v1 + b1));
                } else if (MODE == 1) {
                    float2 rr = *(const float2*)&g_res[(size_t)row*DM + col];
                    float2 a0 = __half22float2(*(const __half2*)&g_yk[(size_t)(2*row)*DM + col]);
                    float2 a1 = __half22float2(*(const __half2*)&g_yk[(size_t)(2*row + 1)*DM + col]);
                    float2 o  = make_float2(v0 + b0 + rr.x + a0.x + a1.x,
                                            v1 + b1 + rr.y + a0.y + a1.y);
                    *(float2*)&Cout[(size_t)row*DM + col] = o;
                } else if (MODE == 2) {
                    __half* dst = (tgt ? g_gv : g_a) + (size_t)(moff + row)*NI + col;
                    *(__half2*)dst = __floats2half2_rn(v0 + b0, v1 + b1);
                } else {
                    int code = g_list[moff + row];
                    float w = g_wts[code];
                    *(__half2*)&g_yk[(size_t)code*DM + col] =
                        __floats2half2_rn(w*(v0 + b0), w*(v1 + b1));
                }
            }
        }
    }
}

// ---------------- launch ----------------
extern "C" void kernel_launch(void* const* d_in, const int* in_sizes, int n_in,
                              void* d_out, int out_size)
{
    const float* x       = (const float*)d_in[0];
    const float* norm1_w = (const float*)d_in[1];
    const float* norm3_w = (const float*)d_in[2];
    const float* gate_w  = (const float*)d_in[3];
    const float* w1      = (const float*)d_in[4];
    const float* b1      = (const float*)d_in[5];
    const float* w2      = (const float*)d_in[6];
    const float* b2      = (const float*)d_in[7];
    const float* w3      = (const float*)d_in[8];
    const float* b3      = (const float*)d_in[9];
    const float* fc1_w   = (const float*)d_in[10];
    const float* fc1_b   = (const float*)d_in[11];
    const float* fc2_w   = (const float*)d_in[12];
    const float* fc2_b   = (const float*)d_in[13];
    float* out = (float*)d_out;

    const int SM_128_128 = 98304;   // 3*(16K+16K)
    const int SM_128_64  = 73728;   // 3*(16K+8K)
    const int SM_64_64   = 49152;   // 3*(8K+8K)
    const int SMA        = 8192*4 + 512;

    static cudaStream_t s2 = nullptr;
    static cudaEvent_t evRoot = nullptr, evA = nullptr, evB = nullptr, evC = nullptr;
    static __half *p_w1, *p_w3, *p_w2, *p_fc1, *p_fc2;
    if (!s2) {
        cudaStreamCreateWithFlags(&s2, cudaStreamNonBlocking);
        cudaEventCreateWithFlags(&evRoot, cudaEventDisableTiming);
        cudaEventCreateWithFlags(&evA, cudaEventDisableTiming);
        cudaEventCreateWithFlags(&evB, cudaEventDisableTiming);
        cudaEventCreateWithFlags(&evC, cudaEventDisableTiming);
        cudaFuncSetAttribute((mma_gemm<0,128,128>), cudaFuncAttributeMaxDynamicSharedMemorySize, SM_128_128);
        cudaFuncSetAttribute((mma_gemm<1,64,64>),   cudaFuncAttributeMaxDynamicSharedMemorySize, SM_64_64);
        cudaFuncSetAttribute((mma_gemm<2,128,64>),  cudaFuncAttributeMaxDynamicSharedMemorySize, SM_128_64);
        cudaFuncSetAttribute((mma_gemm<3,64,64>),   cudaFuncAttributeMaxDynamicSharedMemorySize, SM_64_64);
        cudaFuncSetAttribute(attn_mma_kernel,       cudaFuncAttributeMaxDynamicSharedMemorySize, SMA);
        cudaGetSymbolAddress((void**)&p_w1,  h_w1);
        cudaGetSymbolAddress((void**)&p_w3,  h_w3);
        cudaGetSymbolAddress((void**)&p_w2,  h_w2);
        cudaGetSymbolAddress((void**)&p_fc1, h_fc1);
        cudaGetSymbolAddress((void**)&p_fc2, h_fc2);
    }

    cudaEventRecord(evRoot, 0);
    cudaStreamWaitEvent(s2, evRoot, 0);
    cvt_kernel<<<(NE*NI*DM/4+255)/256, 256, 0, s2>>>((const float4*)w1,    (__half2*)p_w1,  NE*NI*DM/4);
    cvt_kernel<<<(NE*NI*DM/4+255)/256, 256, 0, s2>>>((const float4*)w3,    (__half2*)p_w3,  NE*NI*DM/4);
    cvt_kernel<<<(NE*DM*NI/4+255)/256, 256, 0, s2>>>((const float4*)w2,    (__half2*)p_w2,  NE*DM*NI/4);
    cvt_kernel<<<(ISH*DM/4+255)/256,   256, 0, s2>>>((const float4*)fc1_w, (__half2*)p_fc1, ISH*DM/4);
    cvt_kernel<<<(DM*ISH/4+255)/256,   256, 0, s2>>>((const float4*)fc2_w, (__half2*)p_fc2, DM*ISH/4);
    cudaEventRecord(evC, s2);

    rmsnorm_kernel<0><<<SQ, 256>>>(x, norm1_w, nullptr);
    attn_mma_kernel<<<dim3(SQ/64, NH), 256, SMA>>>(x);
    rmsnorm_kernel<1><<<SQ, 256>>>(nullptr, norm3_w, gate_w);

    cudaEventRecord(evA, 0);
    cudaStreamWaitEvent(s2, evA, 0);
    mma_gemm<0,128,128><<<dim3(ISH/128, SQ/128), 256, SM_128_128, s2>>>(p_fc1, nullptr, nullptr, fc1_b, nullptr);
    cudaEventRecord(evB, s2);

    route_kernel<<<1, 1024>>>();
    cudaStreamWaitEvent(0, evC, 0);
    // up: bx<16 -> w1 -> g_a ; bx>=16 -> w3 -> g_gv  (BM=128, BN=64)
    mma_gemm<2,128,64><<<dim3(2*NI/64, 32, NE), 256, SM_128_64>>>(p_w1, p_w3, nullptr, b1, b3);
    silu_mul_kernel<<<(NSLOT*NI)/1024, 256>>>();
    mma_gemm<3,64,64><<<dim3(DM/64, NSLOT/64, NE), 256, SM_64_64>>>(p_w2, nullptr, nullptr, b2, nullptr);

    cudaStreamWaitEvent(0, evB, 0);
    mma_gemm<1,64,64><<<dim3(DM/64, SQ/64), 256, SM_64_64>>>(p_fc2, nullptr, out, fc2_b, nullptr);
}

// round 16
// speedup vs baseline: 1.0611x; 1.0611x over previous
#include <cuda_runtime.h>
#include <cuda_fp16.h>
#include <math.h>
#include <stdint.h>

#define SQ   2048
#define DM   768
#define NH   12
#define HD   64
#define NE   8
#define NI   1024
#define ISH  2048
#define NSLOT (2*SQ)

// ---------------- device scratch ----------------
__device__ __align__(16) __half g_xn[SQ*DM];
__device__ __align__(16) float g_res[SQ*DM];
__device__ __align__(16) __half g_xf[SQ*DM];
__device__ __align__(16) __half g_t [SQ*ISH];
__device__ __align__(16) __half g_a [NSLOT*NI];
__device__ __align__(16) __half g_gv[NSLOT*NI];
__device__ __align__(16) __half g_h [NSLOT*NI];
__device__ __align__(16) __half g_yk[NSLOT*DM];
__device__ float g_logits[SQ*NE];
__device__ float g_wts[NSLOT];
__device__ int   g_counts[NE];
__device__ int   g_offsets[NE];
__device__ int   g_list[NSLOT];
__device__ __align__(16) __half h_w1 [NE*NI*DM];
__device__ __align__(16) __half h_w3 [NE*NI*DM];
__device__ __align__(16) __half h_w2 [NE*DM*NI];
__device__ __align__(16) __half h_fc1[ISH*DM];
__device__ __align__(16) __half h_fc2[DM*ISH];

// ---------------- helpers ----------------
__device__ __forceinline__ uint32_t smem_u32(const void* p){
    uint32_t a;
    asm("{ .reg .u64 t; cvta.to.shared.u64 t, %1; cvt.u32.u64 %0, t; }" : "=r"(a) : "l"(p));
    return a;
}
__device__ __forceinline__ void mma16(float* d, const uint32_t* a, const uint32_t* b){
    asm volatile("mma.sync.aligned.m16n8k16.row.col.f32.f16.f16.f32 "
        "{%0,%1,%2,%3}, {%4,%5,%6,%7}, {%8,%9}, {%0,%1,%2,%3};"
        : "+f"(d[0]), "+f"(d[1]), "+f"(d[2]), "+f"(d[3])
        : "r"(a[0]), "r"(a[1]), "r"(a[2]), "r"(a[3]), "r"(b[0]), "r"(b[1]));
}
__device__ __forceinline__ void ldm4(uint32_t* r, uint32_t addr){
    asm volatile("ldmatrix.sync.aligned.m8n8.x4.shared.b16 {%0,%1,%2,%3}, [%4];"
        : "=r"(r[0]), "=r"(r[1]), "=r"(r[2]), "=r"(r[3]) : "r"(addr));
}
__device__ __forceinline__ void cpasync16(uint32_t dst, const void* src){
    asm volatile("cp.async.cg.shared.global [%0], [%1], 16;" :: "r"(dst), "l"(src) : "memory");
}
#define CP_COMMIT() asm volatile("cp.async.commit_group;" ::: "memory")

__device__ __forceinline__ float fexp2n(float y){
    y = fminf(fmaxf(y, -126.f), 126.f);
    float r = y + 12582912.f;
    float f = y - (r - 12582912.f);
    float p = 1.3333558146e-3f;
    p = fmaf(p, f, 9.6181291776e-3f);
    p = fmaf(p, f, 5.5504108664e-2f);
    p = fmaf(p, f, 2.4022650696e-1f);
    p = fmaf(p, f, 6.9314718056e-1f);
    p = fmaf(p, f, 1.0f);
    return __int_as_float(__float_as_int(p) + (__float_as_int(r) << 23));
}
__device__ __forceinline__ float fexps17(float s){
    return fexp2n(fmaf(s, 0.18033688011112042f, -17.0f));
}
__device__ __forceinline__ float frcp(float x){
    float y = __int_as_float(0x7EF311C3 - __float_as_int(x));
    y = y * (2.f - x*y);
    y = y * (2.f - x*y);
    y = y * (2.f - x*y);
    return y;
}
__device__ __forceinline__ float fsilu(float a){
    float t = fexp2n(-a * 1.4426950408889634f);
    return a * frcp(1.f + t);
}

// ---------------- fp32 -> fp16 conversion ----------------
__global__ void __launch_bounds__(256) cvt_kernel(const float4* __restrict__ src,
                                                  __half2* __restrict__ dst, int n4)
{
    int i = blockIdx.x * 256 + threadIdx.x;
    if (i < n4) {
        float4 v = src[i];
        dst[2*i]   = __floats2half2_rn(v.x, v.y);
        dst[2*i+1] = __floats2half2_rn(v.z, v.w);
    }
}

// ---------------- rmsnorm ----------------
template<int WHICH>
__global__ void __launch_bounds__(256) rmsnorm_kernel(const float* __restrict__ x,
                                                      const float* __restrict__ w,
                                                      const float* __restrict__ gw)
{
    int n = blockIdx.x;
    int t = threadIdx.x;
    const float* row = (WHICH == 0) ? (x + (size_t)n*DM) : (g_res + (size_t)n*DM);

    float v0 = row[t], v1 = row[t+256], v2 = row[t+512];
    float ss = v0*v0 + v1*v1 + v2*v2;

    __shared__ float red[8];
    __shared__ float part[8][8];
    #pragma unroll
    for (int o = 16; o; o >>= 1) ss += __shfl_down_sync(0xffffffffu, ss, o);
    if ((t & 31) == 0) red[t >> 5] = ss;
    __syncthreads();
    if (t < 8) {
        ss = red[t];
        #pragma unroll
        for (int o = 4; o; o >>= 1) ss += __shfl_down_sync(0xffu, ss, o);
        if (t == 0) red[0] = ss;
    }
    __syncthreads();
    float inv = rsqrtf(red[0] * (1.0f/DM) + 1e-5f);
    float o0 = v0*inv*w[t], o1 = v1*inv*w[t+256], o2 = v2*inv*w[t+512];
    __half* out = (WHICH == 0) ? (g_xn + (size_t)n*DM) : (g_xf + (size_t)n*DM);
    out[t]     = __float2half_rn(o0);
    out[t+256] = __float2half_rn(o1);
    out[t+512] = __float2half_rn(o2);

    if (WHICH == 1) {
        float d[8];
        #pragma unroll
        for (int e = 0; e < 8; e++)
            d[e] = o0*gw[e*DM + t] + o1*gw[e*DM + t + 256] + o2*gw[e*DM + t + 512];
        #pragma unroll
        for (int e = 0; e < 8; e++) {
            #pragma unroll
            for (int o = 16; o; o >>= 1) d[e] += __shfl_down_sync(0xffffffffu, d[e], o);
        }
        if ((t & 31) == 0) {
            #pragma unroll
            for (int e = 0; e < 8; e++) part[t >> 5][e] = d[e];
        }
        __syncthreads();
        if (t < 8) {
            float l = 0.f;
            #pragma unroll
            for (int wv = 0; wv < 8; wv++) l += part[wv][t];
            g_logits[n*NE + t] = l;
        }
    }
}

// ---------------- merged routing ----------------
__global__ void __launch_bounds__(1024) route_kernel()
{
    __shared__ int cnt[NE], off[NE], fill[NE];
    int t = threadIdx.x;
    if (t < NE) { cnt[t] = 0; fill[t] = 0; }
    __syncthreads();

    int eidx[2][2];
    #pragma unroll
    for (int j = 0; j < 2; j++) {
        int n = t*2 + j;
        float lg[NE];
        #pragma unroll
        for (int i = 0; i < NE; i++) lg[i] = g_logits[n*NE + i];
        float m = -1e30f;
        #pragma unroll
        for (int i = 0; i < NE; i++) m = fmaxf(m, lg[i]);
        float s = 0.f;
        #pragma unroll
        for (int i = 0; i < NE; i++) { lg[i] = fexp2n((lg[i] - m) * 1.4426950408889634f); s += lg[i]; }
        float invs = 1.f / s;
        int e0 = -1, e1 = -1; float v0 = -1.f, v1 = -1.f;
        #pragma unroll
        for (int i = 0; i < NE; i++) {
            float v = lg[i] * invs;
            if (v > v0) { v1 = v0; e1 = e0; v0 = v; e0 = i; }
            else if (v > v1) { v1 = v; e1 = i; }
        }
        g_wts[2*n]     = fmaxf(v0, 1e-7f);
        g_wts[2*n + 1] = fmaxf(v1, 1e-7f);
        eidx[j][0] = e0; eidx[j][1] = e1;
        atomicAdd(&cnt[e0], 1);
        atomicAdd(&cnt[e1], 1);
    }
    __syncthreads();
    if (t == 0) {
        int o = 0;
        for (int e = 0; e < NE; e++) { g_counts[e] = cnt[e]; off[e] = o; g_offsets[e] = o; o += cnt[e]; }
    }
    __syncthreads();
    #pragma unroll
    for (int j = 0; j < 2; j++) {
        #pragma unroll
        for (int k = 0; k < 2; k++) {
            int e = eidx[j][k];
            int p = atomicAdd(&fill[e], 1);
            g_list[off[e] + p] = (t*2 + j)*2 + k;
        }
    }
}

// ---------------- attention: all-fp16 mma + ldmatrix + scaled fast exp ----------------
__global__ void __launch_bounds__(256) attn_mma_kernel(const float* __restrict__ x)
{
    int q0 = blockIdx.x * 64;
    int h  = blockIdx.y;

    extern __shared__ __align__(16) uint32_t sm[];
    uint32_t* Qs = sm;
    uint32_t* Ks = sm + 2048;
    uint32_t* Vt = sm + 4096;
    uint32_t* Ps = sm + 6144;
    float* rssm  = (float*)(sm + 8192);

    int tid = threadIdx.x, lane = tid & 31, wid = tid >> 5;
    int wm = wid & 3, wn = wid >> 2, gid = lane >> 2, qid = lane & 3;

    uint32_t qBase = smem_u32(Qs), kBase = smem_u32(Ks);
    uint32_t vBase = smem_u32(Vt), pBase = smem_u32(Ps);

    int aRow = wm*16 + (lane & 15);
    uint32_t aHalf = (uint32_t)(lane >> 4) * 16u;
    uint32_t aXor  = (uint32_t)((aRow & 7) << 4);
    uint32_t aTerm = (uint32_t)(aRow * 128);
    int bRow = wn*32 + ((lane >> 4) << 3) + (lane & 7);
    uint32_t bHalf = (uint32_t)((lane >> 3) & 1) * 16u;
    uint32_t bXor  = (uint32_t)((bRow & 7) << 4);
    uint32_t bTerm0 = (uint32_t)(bRow * 128);
    uint32_t bTerm1 = (uint32_t)((bRow + 16) * 128);

    {
        int r = tid >> 2, b0 = (tid & 3) * 32;
        const __half* src = g_xn + (size_t)(q0 + r)*DM + h*HD + b0/2;
        char* qb = (char*)Qs;
        *(uint4*)(qb + r*128 + ((b0      ) ^ ((r & 7) << 4))) = *(const uint4*)src;
        *(uint4*)(qb + r*128 + ((b0 + 16) ^ ((r & 7) << 4))) = *(const uint4*)(src + 8);
    }

    float acc_o[4][4] = {};
    float rs0 = 0.f, rs1 = 0.f;
    int r0 = wm*16 + gid;

    for (int kt = 0; kt < SQ/64; kt++) {
        __syncthreads();
        {
            int r = tid >> 2, b0 = (tid & 3) * 32;
            const __half* src = g_xn + (size_t)(kt*64 + r)*DM + h*HD + b0/2;
            uint4 u0 = *(const uint4*)src;
            uint4 u1 = *(const uint4*)(src + 8);
            char* kb = (char*)Ks;
            *(uint4*)(kb + r*128 + ((b0      ) ^ ((r & 7) << 4))) = u0;
            *(uint4*)(kb + r*128 + ((b0 + 16) ^ ((r & 7) << 4))) = u1;

            uint32_t w[8] = {u0.x,u0.y,u0.z,u0.w,u1.x,u1.y,u1.z,u1.w};
            uint32_t pw[8];
            #pragma unroll
            for (int j = 0; j < 8; j++) pw[j] = __shfl_xor_sync(0xffffffffu, w[j], 4);
            if ((r & 1) == 0) {
                const __half* mh = (const __half*)w;
                const __half* ph = (const __half*)pw;
                int wt = r >> 1;
                int d0 = b0 >> 1;
                #pragma unroll
                for (int d = 0; d < 16; d++) {
                    uint32_t val = ((uint32_t)__half_as_ushort(ph[d]) << 16)
                                 |  (uint32_t)__half_as_ushort(mh[d]);
                    int dd = d0 + d;
                    Vt[dd*32 + (wt ^ ((dd & 7) << 2))] = val;
                }
            }
        }
        __syncthreads();

        float acc_s[4][4] = {};
        #pragma unroll
        for (int kk = 0; kk < 4; kk++) {
            uint32_t kbyte = (uint32_t)(kk * 32);
            uint32_t aoff = (kbyte + aHalf) ^ aXor;
            uint32_t boff = (kbyte + bHalf) ^ bXor;
            uint32_t af[4], b0f[4], b1f[4];
            ldm4(af,  qBase + aTerm + aoff);
            ldm4(b0f, kBase + bTerm0 + boff);
            ldm4(b1f, kBase + bTerm1 + boff);
            mma16(acc_s[0], af, b0f);
            mma16(acc_s[1], af, b0f + 2);
            mma16(acc_s[2], af, b1f);
            mma16(acc_s[3], af, b1f + 2);
        }

        float p0 = 0.f, p1 = 0.f;
        #pragma unroll
        for (int ni = 0; ni < 4; ni++) {
            float e0 = fexps17(acc_s[ni][0]);
            float e1 = fexps17(acc_s[ni][1]);
            float e2 = fexps17(acc_s[ni][2]);
            float e3 = fexps17(acc_s[ni][3]);
            p0 += e0 + e1;
            p1 += e2 + e3;
            int cw = (wn*32 + 8*ni + 2*qid) >> 1;
            __half2 h01 = __floats2half2_rn(e0, e1);
            __half2 h23 = __floats2half2_rn(e2, e3);
            Ps[r0*32 + (cw ^ ((r0 & 7) << 2))] = *(uint32_t*)&h01;
            int r1 = r0 + 8;
            Ps[r1*32 + (cw ^ ((r1 & 7) << 2))] = *(uint32_t*)&h23;
        }
        p0 += __shfl_xor_sync(0xffffffffu, p0, 1);
        p0 += __shfl_xor_sync(0xffffffffu, p0, 2);
        p1 += __shfl_xor_sync(0xffffffffu, p1, 1);
        p1 += __shfl_xor_sync(0xffffffffu, p1, 2);
        rs0 += p0; rs1 += p1;
        __syncthreads();

        #pragma unroll
        for (int kk = 0; kk < 4; kk++) {
            uint32_t kbyte = (uint32_t)(kk * 32);
            uint32_t aoff = (kbyte + aHalf) ^ aXor;
            uint32_t boff = (kbyte + bHalf) ^ bXor;
            uint32_t af[4], b0f[4], b1f[4];
            ldm4(af,  pBase + aTerm + aoff);
            ldm4(b0f, vBase + bTerm0 + boff);
            ldm4(b1f, vBase + bTerm1 + boff);
            mma16(acc_o[0], af, b0f);
            mma16(acc_o[1], af, b0f + 2);
            mma16(acc_o[2], af, b1f);
            mma16(acc_o[3], af, b1f + 2);
        }
    }

    if (qid == 0) {
        rssm[wn*64 + r0]     = rs0;
        rssm[wn*64 + r0 + 8] = rs1;
    }
    __syncthreads();
    float inv0 = 1.f / (rssm[r0]     + rssm[64 + r0]);
    float inv1 = 1.f / (rssm[r0 + 8] + rssm[64 + r0 + 8]);

    #pragma unroll
    for (int ni = 0; ni < 4; ni++) {
        int col = h*HD + wn*32 + 8*ni + 2*qid;
        size_t gi0 = (size_t)(q0 + r0)*DM + col;
        size_t gi1 = (size_t)(q0 + r0 + 8)*DM + col;
        float2 x0 = *(const float2*)&x[gi0];
        float2 x1 = *(const float2*)&x[gi1];
        float2 o0 = make_float2(x0.x + acc_o[ni][0]*inv0, x0.y + acc_o[ni][1]*inv0);
        float2 o1 = make_float2(x1.x + acc_o[ni][2]*inv1, x1.y + acc_o[ni][3]*inv1);
        *(float2*)&g_res[gi0] = o0;
        *(float2*)&g_res[gi1] = o1;
    }
}

// ---------------- h = silu(a) * g -> fp16 ----------------
__global__ void silu_mul_kernel()
{
    int i = (blockIdx.x * 256 + threadIdx.x) * 4;
    __half2 a01 = *(__half2*)&g_a[i],  a23 = *(__half2*)&g_a[i+2];
    __half2 g01 = *(__half2*)&g_gv[i], g23 = *(__half2*)&g_gv[i+2];
    float2 a0 = __half22float2(a01), a2 = __half22float2(a23);
    float2 g0 = __half22float2(g01), g2 = __half22float2(g23);
    *(__half2*)&g_h[i]   = __floats2half2_rn(fsilu(a0.x)*g0.x, fsilu(a0.y)*g0.y);
    *(__half2*)&g_h[i+2] = __floats2half2_rn(fsilu(a2.x)*g2.x, fsilu(a2.y)*g2.y);
}

// ---------------- fp16 mma GEMM, ldmatrix, BM x BN tiles ----------------
// MODE 0: fc1 : A=g_xf          B=h_fc1     -> g_t(fp16) silu(acc+bias)
// MODE 1: fc2 : A=g_t           B=h_fc2     -> out       acc+bias+res+yk0+yk1
// MODE 2: up  : A=g_xf (gather) B=h_w1/h_w3 -> g_a/g_gv  acc+bias (fp16)
// MODE 3: dn  : A=g_h (compact) B=h_w2      -> g_yk(fp16) wts*(acc+bias) scatter
template<int MODE, int BM, int BN>
__global__ void __launch_bounds__(256, 2) mma_gemm(const __half* __restrict__ Bw,
                                                   const __half* __restrict__ Bw2,
                                                   float* __restrict__ Cout,
                                                   const float* __restrict__ bias,
                                                   const float* __restrict__ bias2)
{
    constexpr int KD  = (MODE==1) ? ISH : (MODE==3 ? NI : DM);
    constexpr int NC  = KD / 64;
    constexpr int NN  = (MODE==0) ? ISH : (MODE==2 ? NI : DM);
    constexpr int AW  = BM * 32;
    constexpr int BW  = BN * 32;
    constexpr int BOFF = 3 * AW;
    constexpr int WMN = (BM==128) ? 4 : 2;
    constexpr int WNN = 8 / WMN;
    constexpr int WNW = BN / WNN;
    constexpr int NIT = WNW / 8;
    constexpr int TPRA = 256 / BM;
    constexpr int NCA  = 128 / TPRA / 16;
    constexpr int TPRB = 256 / BN;
    constexpr int NCB  = 128 / TPRB / 16;

    int bx = blockIdx.x;
    int tgt = 0;
    const __half* Bsel = Bw;
    const float* bsel = bias;
    if (MODE == 2 && bx >= NI/BN) { tgt = 1; bx -= NI/BN; Bsel = Bw2; bsel = bias2; }
    int n0 = bx * BN;
    int m0 = blockIdx.y * BM;
    int M = SQ, moff = 0;

    if (MODE >= 2) {
        int e = blockIdx.z;
        int cnt = g_counts[e];
        if (m0 >= cnt) return;
        M = cnt; moff = g_offsets[e];
        Bsel += (size_t)e * NN * KD;
        bsel += (size_t)e * NN;
    }

    extern __shared__ __align__(128) uint32_t smu[];
    uint32_t smbase = smem_u32(smu);

    int tid = threadIdx.x, lane = tid & 31, wid = tid >> 5;
    int wm = wid & (WMN-1), wn = wid / WMN;
    int gid = lane >> 2, qid = lane & 3;

    int ra = tid / TPRA;
    int ab0 = (tid % TPRA) * (128 / TPRA);
    int hofa[NCA]; uint32_t sba[NCA];
    #pragma unroll
    for (int i = 0; i < NCA; i++) {
        int bo = ab0 + i*16;
        hofa[i] = bo >> 1;
        sba[i] = (uint32_t)(ra*128 + (bo ^ ((ra & 7) << 4)));
    }
    int mrow = m0 + ra; if (mrow > M - 1) mrow = M - 1;
    const __half* arow;
    if      (MODE == 2) arow = g_xf + (size_t)(g_list[moff + mrow] >> 1) * DM;
    else if (MODE == 3) arow = g_h  + (size_t)(moff + mrow) * NI;
    else if (MODE == 1) arow = g_t  + (size_t)mrow * ISH;
    else                arow = g_xf + (size_t)mrow * DM;

    int rb = tid / TPRB;
    int bb0 = (tid % TPRB) * (128 / TPRB);
    const __half* brow = Bsel + (size_t)(n0 + rb) * KD;
    int hofb[NCB]; uint32_t sbb[NCB];
    #pragma unroll
    for (int i = 0; i < NCB; i++) {
        int bo = bb0 + i*16;
        hofb[i] = bo >> 1;
        sbb[i] = (uint32_t)(rb*128 + (bo ^ ((rb & 7) << 4)));
    }

    int aRow0 = 32*wm + (lane & 15);
    uint32_t aHalf = (uint32_t)(lane >> 4) * 16u;
    uint32_t aXor  = (uint32_t)((aRow0 & 7) << 4);
    uint32_t aTerm[2];
    aTerm[0] = (uint32_t)(aRow0 * 128);
    aTerm[1] = (uint32_t)((aRow0 + 16) * 128);
    int bRow0 = WNW*wn + ((lane >> 4) << 3) + (lane & 7);
    uint32_t bHalf = (uint32_t)((lane >> 3) & 1) * 16u;
    uint32_t bXor  = (uint32_t)((bRow0 & 7) << 4);
    uint32_t bTerm[NIT/2 > 0 ? NIT/2 : 1];
    #pragma unroll
    for (int j = 0; j < NIT/2; j++) bTerm[j] = (uint32_t)((bRow0 + 16*j) * 128);

#define ISSUE_CHUNK(KC) do { \
        int _kc = (KC); \
        int _st = _kc % 3; \
        uint32_t _da = smbase + (uint32_t)(_st * AW * 4); \
        uint32_t _db = smbase + (uint32_t)((BOFF + _st * BW) * 4); \
        const __half* _as = arow + _kc*64; \
        const __half* _bs = brow + _kc*64; \
        _Pragma("unroll") \
        for (int _i = 0; _i < NCA; _i++) cpasync16(_da + sba[_i], _as + hofa[_i]); \
        _Pragma("unroll") \
        for (int _i = 0; _i < NCB; _i++) cpasync16(_db + sbb[_i], _bs + hofb[_i]); \
        CP_COMMIT(); \
    } while (0)

    ISSUE_CHUNK(0);
    ISSUE_CHUNK(1);

    float acc[2][NIT][4] = {};

    for (int kc = 0; kc < NC; kc++) {
        if (kc == NC - 1) { asm volatile("cp.async.wait_group 0;" ::: "memory"); }
        else              { asm volatile("cp.async.wait_group 1;" ::: "memory"); }
        __syncthreads();
        if (kc + 2 < NC) ISSUE_CHUNK(kc + 2);

        int st = kc % 3;
        uint32_t aBase = smbase + (uint32_t)(st * AW * 4);
        uint32_t bBase = smbase + (uint32_t)((BOFF + st * BW) * 4);
        #pragma unroll
        for (int kk = 0; kk < 4; kk++) {
            uint32_t kbyte = (uint32_t)(kk * 32);
            uint32_t aoff = (kbyte + aHalf) ^ aXor;
            uint32_t boff = (kbyte + bHalf) ^ bXor;
            uint32_t af[2][4], bf[NIT][2];
            ldm4(af[0], aBase + aTerm[0] + aoff);
            ldm4(af[1], aBase + aTerm[1] + aoff);
            #pragma unroll
            for (int j = 0; j < NIT/2; j++) {
                uint32_t r4[4];
                ldm4(r4, bBase + bTerm[j] + boff);
                bf[2*j][0]   = r4[0]; bf[2*j][1]   = r4[1];
                bf[2*j+1][0] = r4[2]; bf[2*j+1][1] = r4[3];
            }
            #pragma unroll
            for (int mi = 0; mi < 2; mi++)
                #pragma unroll
                for (int ni = 0; ni < NIT; ni++)
                    mma16(acc[mi][ni], af[mi], bf[ni]);
        }
    }
#undef ISSUE_CHUNK

    #pragma unroll
    for (int mi = 0; mi < 2; mi++) {
        #pragma unroll
        for (int half = 0; half < 2; half++) {
            int row = m0 + 32*wm + 16*mi + gid + 8*half;
            if (MODE >= 2 && row >= M) continue;
            #pragma unroll
            for (int ni = 0; ni < NIT; ni++) {
                float v0 = acc[mi][ni][2*half + 0];
                float v1 = acc[mi][ni][2*half + 1];
                int col = n0 + WNW*wn + 8*ni + 2*qid;
                float b0 = bsel[col], b1 = bsel[col + 1];
                if (MODE == 0) {
                    *(__half2*)&g_t[(size_t)row*ISH + col] =
                        __floats2half2_rn(fsilu(v0 + b0), fsilu(v1 + b1));
                } else if (MODE == 1) {
                    float2 rr = *(const float2*)&g_res[(size_t)row*DM + col];
                    float2 a0 = __half22float2(*(const __half2*)&g_yk[(size_t)(2*row)*DM + col]);
                    float2 a1 = __half22float2(*(const __half2*)&g_yk[(size_t)(2*row + 1)*DM + col]);
                    float2 o  = make_float2(v0 + b0 + rr.x + a0.x + a1.x,
                                            v1 + b1 + rr.y + a0.y + a1.y);
                    *(float2*)&Cout[(size_t)row*DM + col] = o;
                } else if (MODE == 2) {
                    __half* dst = (tgt ? g_gv : g_a) + (size_t)(moff + row)*NI + col;
                    *(__half2*)dst = __floats2half2_rn(v0 + b0, v1 + b1);
                } else {
                    int code = g_list[moff + row];
                    float w = g_wts[code];
                    *(__half2*)&g_yk[(size_t)code*DM + col] =
                        __floats2half2_rn(w*(v0 + b0), w*(v1 + b1));
                }
            }
        }
    }
}

// ---------------- launch ----------------
extern "C" void kernel_launch(void* const* d_in, const int* in_sizes, int n_in,
                              void* d_out, int out_size)
{
    const float* x       = (const float*)d_in[0];
    const float* norm1_w = (const float*)d_in[1];
    const float* norm3_w = (const float*)d_in[2];
    const float* gate_w  = (const float*)d_in[3];
    const float* w1      = (const float*)d_in[4];
    const float* b1      = (const float*)d_in[5];
    const float* w2      = (const float*)d_in[6];
    const float* b2      = (const float*)d_in[7];
    const float* w3      = (const float*)d_in[8];
    const float* b3      = (const float*)d_in[9];
    const float* fc1_w   = (const float*)d_in[10];
    const float* fc1_b   = (const float*)d_in[11];
    const float* fc2_w   = (const float*)d_in[12];
    const float* fc2_b   = (const float*)d_in[13];
    float* out = (float*)d_out;

    const int SM_128_128 = 98304;
    const int SM_64_128  = 73728;
    const int SM_64_64   = 49152;
    const int SMA        = 8192*4 + 512;

    static cudaStream_t s2 = nullptr;
    static cudaEvent_t evRoot = nullptr, evA = nullptr, evB = nullptr, evC = nullptr;
    static __half *p_w1, *p_w3, *p_w2, *p_fc1, *p_fc2;
    if (!s2) {
        cudaStreamCreateWithFlags(&s2, cudaStreamNonBlocking);
        cudaEventCreateWithFlags(&evRoot, cudaEventDisableTiming);
        cudaEventCreateWithFlags(&evA, cudaEventDisableTiming);
        cudaEventCreateWithFlags(&evB, cudaEventDisableTiming);
        cudaEventCreateWithFlags(&evC, cudaEventDisableTiming);
        cudaFuncSetAttribute((mma_gemm<0,128,128>), cudaFuncAttributeMaxDynamicSharedMemorySize, SM_128_128);
        cudaFuncSetAttribute((mma_gemm<1,64,64>),   cudaFuncAttributeMaxDynamicSharedMemorySize, SM_64_64);
        cudaFuncSetAttribute((mma_gemm<2,128,128>), cudaFuncAttributeMaxDynamicSharedMemorySize, SM_128_128);
        cudaFuncSetAttribute((mma_gemm<3,64,128>),  cudaFuncAttributeMaxDynamicSharedMemorySize, SM_64_128);
        cudaFuncSetAttribute(attn_mma_kernel,       cudaFuncAttributeMaxDynamicSharedMemorySize, SMA);
        cudaGetSymbolAddress((void**)&p_w1,  h_w1);
        cudaGetSymbolAddress((void**)&p_w3,  h_w3);
        cudaGetSymbolAddress((void**)&p_w2,  h_w2);
        cudaGetSymbolAddress((void**)&p_fc1, h_fc1);
        cudaGetSymbolAddress((void**)&p_fc2, h_fc2);
    }

    cudaEventRecord(evRoot, 0);
    cudaStreamWaitEvent(s2, evRoot, 0);
    cvt_kernel<<<(NE*NI*DM/4+255)/256, 256, 0, s2>>>((const float4*)w1,    (__half2*)p_w1,  NE*NI*DM/4);
    cvt_kernel<<<(NE*NI*DM/4+255)/256, 256, 0, s2>>>((const float4*)w3,    (__half2*)p_w3,  NE*NI*DM/4);
    cvt_kernel<<<(NE*DM*NI/4+255)/256, 256, 0, s2>>>((const float4*)w2,    (__half2*)p_w2,  NE*DM*NI/4);
    cvt_kernel<<<(ISH*DM/4+255)/256,   256, 0, s2>>>((const float4*)fc1_w, (__half2*)p_fc1, ISH*DM/4);
    cvt_kernel<<<(DM*ISH/4+255)/256,   256, 0, s2>>>((const float4*)fc2_w, (__half2*)p_fc2, DM*ISH/4);
    cudaEventRecord(evC, s2);

    rmsnorm_kernel<0><<<SQ, 256>>>(x, norm1_w, nullptr);
    attn_mma_kernel<<<dim3(SQ/64, NH), 256, SMA>>>(x);
    rmsnorm_kernel<1><<<SQ, 256>>>(nullptr, norm3_w, gate_w);

    cudaEventRecord(evA, 0);
    cudaStreamWaitEvent(s2, evA, 0);
    mma_gemm<0,128,128><<<dim3(ISH/128, SQ/128), 256, SM_128_128, s2>>>(p_fc1, nullptr, nullptr, fc1_b, nullptr);
    cudaEventRecord(evB, s2);

    route_kernel<<<1, 1024>>>();
    cudaStreamWaitEvent(0, evC, 0);
    // up: R14 config (BM=128, BN=128, merged w1/w3)
    mma_gemm<2,128,128><<<dim3(2*NI/128, 32, NE), 256, SM_128_128>>>(p_w1, p_w3, nullptr, b1, b3);
    silu_mul_kernel<<<(NSLOT*NI)/1024, 256>>>();
    // dn: R14 config (BM=64, BN=128)
    mma_gemm<3,64,128><<<dim3(DM/128, NSLOT/64, NE), 256, SM_64_128>>>(p_w2, nullptr, nullptr, b2, nullptr);

    cudaStreamWaitEvent(0, evB, 0);
    // fc2: BN=64 (only place where tail dominates: 192 -> 384 CTAs)
    mma_gemm<1,64,64><<<dim3(DM/64, SQ/64), 256, SM_64_64>>>(p_fc2, nullptr, out, fc2_b, nullptr);
}

// round 17
// speedup vs baseline: 1.0787x; 1.0166x over previous
#include <cuda_runtime.h>
#include <cuda_fp16.h>
#include <math.h>
#include <stdint.h>

#define SQ   2048
#define DM   768
#define NH   12
#define HD   64
#define NE   8
#define NI   1024
#define ISH  2048
#define NSLOT (2*SQ)

// ---------------- device scratch ----------------
__device__ __align__(16) __half g_xn[SQ*DM];
__device__ __align__(16) float g_res[SQ*DM];
__device__ __align__(16) __half g_xf[SQ*DM];
__device__ __align__(16) __half g_t [SQ*ISH];
__device__ __align__(16) __half g_a [NSLOT*NI];
__device__ __align__(16) __half g_gv[NSLOT*NI];
__device__ __align__(16) __half g_h [NSLOT*NI];
__device__ __align__(16) __half g_yk[NSLOT*DM];
__device__ float g_logits[SQ*NE];
__device__ float g_wts[NSLOT];
__device__ int   g_counts[NE];
__device__ int   g_offsets[NE];
__device__ int   g_list[NSLOT];
__device__ __align__(16) __half h_w1 [NE*NI*DM];
__device__ __align__(16) __half h_w3 [NE*NI*DM];
__device__ __align__(16) __half h_w2 [NE*DM*NI];
__device__ __align__(16) __half h_fc1[ISH*DM];
__device__ __align__(16) __half h_fc2[DM*ISH];

// ---------------- helpers ----------------
__device__ __forceinline__ uint32_t smem_u32(const void* p){
    uint32_t a;
    asm("{ .reg .u64 t; cvta.to.shared.u64 t, %1; cvt.u32.u64 %0, t; }" : "=r"(a) : "l"(p));
    return a;
}
__device__ __forceinline__ void mma16(float* d, const uint32_t* a, const uint32_t* b){
    asm volatile("mma.sync.aligned.m16n8k16.row.col.f32.f16.f16.f32 "
        "{%0,%1,%2,%3}, {%4,%5,%6,%7}, {%8,%9}, {%0,%1,%2,%3};"
        : "+f"(d[0]), "+f"(d[1]), "+f"(d[2]), "+f"(d[3])
        : "r"(a[0]), "r"(a[1]), "r"(a[2]), "r"(a[3]), "r"(b[0]), "r"(b[1]));
}
__device__ __forceinline__ void ldm4(uint32_t* r, uint32_t addr){
    asm volatile("ldmatrix.sync.aligned.m8n8.x4.shared.b16 {%0,%1,%2,%3}, [%4];"
        : "=r"(r[0]), "=r"(r[1]), "=r"(r[2]), "=r"(r[3]) : "r"(addr));
}
__device__ __forceinline__ void cpasync16(uint32_t dst, const void* src){
    asm volatile("cp.async.cg.shared.global [%0], [%1], 16;" :: "r"(dst), "l"(src) : "memory");
}
#define CP_COMMIT() asm volatile("cp.async.commit_group;" ::: "memory")

__device__ __forceinline__ float fexp2n(float y){
    y = fminf(fmaxf(y, -126.f), 126.f);
    float r = y + 12582912.f;
    float f = y - (r - 12582912.f);
    float p = 1.3333558146e-3f;
    p = fmaf(p, f, 9.6181291776e-3f);
    p = fmaf(p, f, 5.5504108664e-2f);
    p = fmaf(p, f, 2.4022650696e-1f);
    p = fmaf(p, f, 6.9314718056e-1f);
    p = fmaf(p, f, 1.0f);
    return __int_as_float(__float_as_int(p) + (__float_as_int(r) << 23));
}
__device__ __forceinline__ float fexps17(float s){
    return fexp2n(fmaf(s, 0.18033688011112042f, -17.0f));
}
__device__ __forceinline__ float frcp(float x){
    float y = __int_as_float(0x7EF311C3 - __float_as_int(x));
    y = y * (2.f - x*y);
    y = y * (2.f - x*y);
    y = y * (2.f - x*y);
    return y;
}
__device__ __forceinline__ float fsilu(float a){
    float t = fexp2n(-a * 1.4426950408889634f);
    return a * frcp(1.f + t);
}

// ---------------- fp32 -> fp16 conversion ----------------
__global__ void __launch_bounds__(256) cvt_kernel(const float4* __restrict__ src,
                                                  __half2* __restrict__ dst, int n4)
{
    int i = blockIdx.x * 256 + threadIdx.x;
    if (i < n4) {
        float4 v = src[i];
        dst[2*i]   = __floats2half2_rn(v.x, v.y);
        dst[2*i+1] = __floats2half2_rn(v.z, v.w);
    }
}

// ---------------- rmsnorm ----------------
template<int WHICH>
__global__ void __launch_bounds__(256) rmsnorm_kernel(const float* __restrict__ x,
                                                      const float* __restrict__ w,
                                                      const float* __restrict__ gw)
{
    int n = blockIdx.x;
    int t = threadIdx.x;
    const float* row = (WHICH == 0) ? (x + (size_t)n*DM) : (g_res + (size_t)n*DM);

    float v0 = row[t], v1 = row[t+256], v2 = row[t+512];
    float ss = v0*v0 + v1*v1 + v2*v2;

    __shared__ float red[8];
    __shared__ float part[8][8];
    #pragma unroll
    for (int o = 16; o; o >>= 1) ss += __shfl_down_sync(0xffffffffu, ss, o);
    if ((t & 31) == 0) red[t >> 5] = ss;
    __syncthreads();
    if (t < 8) {
        ss = red[t];
        #pragma unroll
        for (int o = 4; o; o >>= 1) ss += __shfl_down_sync(0xffu, ss, o);
        if (t == 0) red[0] = ss;
    }
    __syncthreads();
    float inv = rsqrtf(red[0] * (1.0f/DM) + 1e-5f);
    float o0 = v0*inv*w[t], o1 = v1*inv*w[t+256], o2 = v2*inv*w[t+512];
    __half* out = (WHICH == 0) ? (g_xn + (size_t)n*DM) : (g_xf + (size_t)n*DM);
    out[t]     = __float2half_rn(o0);
    out[t+256] = __float2half_rn(o1);
    out[t+512] = __float2half_rn(o2);

    if (WHICH == 1) {
        float d[8];
        #pragma unroll
        for (int e = 0; e < 8; e++)
            d[e] = o0*gw[e*DM + t] + o1*gw[e*DM + t + 256] + o2*gw[e*DM + t + 512];
        #pragma unroll
        for (int e = 0; e < 8; e++) {
            #pragma unroll
            for (int o = 16; o; o >>= 1) d[e] += __shfl_down_sync(0xffffffffu, d[e], o);
        }
        if ((t & 31) == 0) {
            #pragma unroll
            for (int e = 0; e < 8; e++) part[t >> 5][e] = d[e];
        }
        __syncthreads();
        if (t < 8) {
            float l = 0.f;
            #pragma unroll
            for (int wv = 0; wv < 8; wv++) l += part[wv][t];
            g_logits[n*NE + t] = l;
        }
    }
}

// ---------------- merged routing ----------------
__global__ void __launch_bounds__(1024) route_kernel()
{
    __shared__ int cnt[NE], off[NE], fill[NE];
    int t = threadIdx.x;
    if (t < NE) { cnt[t] = 0; fill[t] = 0; }
    __syncthreads();

    int eidx[2][2];
    #pragma unroll
    for (int j = 0; j < 2; j++) {
        int n = t*2 + j;
        float lg[NE];
        #pragma unroll
        for (int i = 0; i < NE; i++) lg[i] = g_logits[n*NE + i];
        float m = -1e30f;
        #pragma unroll
        for (int i = 0; i < NE; i++) m = fmaxf(m, lg[i]);
        float s = 0.f;
        #pragma unroll
        for (int i = 0; i < NE; i++) { lg[i] = fexp2n((lg[i] - m) * 1.4426950408889634f); s += lg[i]; }
        float invs = 1.f / s;
        int e0 = -1, e1 = -1; float v0 = -1.f, v1 = -1.f;
        #pragma unroll
        for (int i = 0; i < NE; i++) {
            float v = lg[i] * invs;
            if (v > v0) { v1 = v0; e1 = e0; v0 = v; e0 = i; }
            else if (v > v1) { v1 = v; e1 = i; }
        }
        g_wts[2*n]     = fmaxf(v0, 1e-7f);
        g_wts[2*n + 1] = fmaxf(v1, 1e-7f);
        eidx[j][0] = e0; eidx[j][1] = e1;
        atomicAdd(&cnt[e0], 1);
        atomicAdd(&cnt[e1], 1);
    }
    __syncthreads();
    if (t == 0) {
        int o = 0;
        for (int e = 0; e < NE; e++) { g_counts[e] = cnt[e]; off[e] = o; g_offsets[e] = o; o += cnt[e]; }
    }
    __syncthreads();
    #pragma unroll
    for (int j = 0; j < 2; j++) {
        #pragma unroll
        for (int k = 0; k < 2; k++) {
            int e = eidx[j][k];
            int p = atomicAdd(&fill[e], 1);
            g_list[off[e] + p] = (t*2 + j)*2 + k;
        }
    }
}

// ---------------- attention: all-fp16 mma + ldmatrix + K-tile register prefetch ----------------
__global__ void __launch_bounds__(256) attn_mma_kernel(const float* __restrict__ x)
{
    int q0 = blockIdx.x * 64;
    int h  = blockIdx.y;

    extern __shared__ __align__(16) uint32_t sm[];
    uint32_t* Qs = sm;
    uint32_t* Ks = sm + 2048;
    uint32_t* Vt = sm + 4096;
    uint32_t* Ps = sm + 6144;
    float* rssm  = (float*)(sm + 8192);

    int tid = threadIdx.x, lane = tid & 31, wid = tid >> 5;
    int wm = wid & 3, wn = wid >> 2, gid = lane >> 2, qid = lane & 3;

    uint32_t qBase = smem_u32(Qs), kBase = smem_u32(Ks);
    uint32_t vBase = smem_u32(Vt), pBase = smem_u32(Ps);

    int aRow = wm*16 + (lane & 15);
    uint32_t aHalf = (uint32_t)(lane >> 4) * 16u;
    uint32_t aXor  = (uint32_t)((aRow & 7) << 4);
    uint32_t aTerm = (uint32_t)(aRow * 128);
    int bRow = wn*32 + ((lane >> 4) << 3) + (lane & 7);
    uint32_t bHalf = (uint32_t)((lane >> 3) & 1) * 16u;
    uint32_t bXor  = (uint32_t)((bRow & 7) << 4);
    uint32_t bTerm0 = (uint32_t)(bRow * 128);
    uint32_t bTerm1 = (uint32_t)((bRow + 16) * 128);

    // loader lane geometry
    int lr = tid >> 2, lb0 = (tid & 3) * 32;
    const __half* lsrc0 = g_xn + (size_t)lr*DM + h*HD + lb0/2;

    // load Q tile fp16 (64 rows x 128B), swizzled
    {
        const __half* src = lsrc0 + (size_t)q0*DM;
        char* qb = (char*)Qs;
        *(uint4*)(qb + lr*128 + ((lb0      ) ^ ((lr & 7) << 4))) = *(const uint4*)src;
        *(uint4*)(qb + lr*128 + ((lb0 + 16) ^ ((lr & 7) << 4))) = *(const uint4*)(src + 8);
    }

    // prefetch K tile 0 into registers
    uint4 u0 = *(const uint4*)lsrc0;
    uint4 u1 = *(const uint4*)(lsrc0 + 8);

    float acc_o[4][4] = {};
    float rs0 = 0.f, rs1 = 0.f;
    int r0 = wm*16 + gid;

    for (int kt = 0; kt < SQ/64; kt++) {
        __syncthreads();   // previous-iteration consumers of Ks/Vt/Ps done
        // store prefetched K tile -> Ks + transposed Vt
        {
            char* kb = (char*)Ks;
            *(uint4*)(kb + lr*128 + ((lb0      ) ^ ((lr & 7) << 4))) = u0;
            *(uint4*)(kb + lr*128 + ((lb0 + 16) ^ ((lr & 7) << 4))) = u1;

            uint32_t w[8] = {u0.x,u0.y,u0.z,u0.w,u1.x,u1.y,u1.z,u1.w};
            uint32_t pw[8];
            #pragma unroll
            for (int j = 0; j < 8; j++) pw[j] = __shfl_xor_sync(0xffffffffu, w[j], 4);
            if ((lr & 1) == 0) {
                const __half* mh = (const __half*)w;
                const __half* ph = (const __half*)pw;
                int wt = lr >> 1;
                int d0 = lb0 >> 1;
                #pragma unroll
                for (int d = 0; d < 16; d++) {
                    uint32_t val = ((uint32_t)__half_as_ushort(ph[d]) << 16)
                                 |  (uint32_t)__half_as_ushort(mh[d]);
                    int dd = d0 + d;
                    Vt[dd*32 + (wt ^ ((dd & 7) << 2))] = val;
                }
            }
        }
        __syncthreads();

        // prefetch next K tile (overlaps with QK/exp/PV below)
        if (kt + 1 < SQ/64) {
            const __half* src = lsrc0 + (size_t)(kt + 1)*64*DM;
            u0 = *(const uint4*)src;
            u1 = *(const uint4*)(src + 8);
        }

        // S = Q K^T
        float acc_s[4][4] = {};
        #pragma unroll
        for (int kk = 0; kk < 4; kk++) {
            uint32_t kbyte = (uint32_t)(kk * 32);
            uint32_t aoff = (kbyte + aHalf) ^ aXor;
            uint32_t boff = (kbyte + bHalf) ^ bXor;
            uint32_t af[4], b0f[4], b1f[4];
            ldm4(af,  qBase + aTerm + aoff);
            ldm4(b0f, kBase + bTerm0 + boff);
            ldm4(b1f, kBase + bTerm1 + boff);
            mma16(acc_s[0], af, b0f);
            mma16(acc_s[1], af, b0f + 2);
            mma16(acc_s[2], af, b1f);
            mma16(acc_s[3], af, b1f + 2);
        }

        // P' = 2^(s*log2e/8 - 17) -> fp16 Ps + fp32 row sums
        float p0 = 0.f, p1 = 0.f;
        #pragma unroll
        for (int ni = 0; ni < 4; ni++) {
            float e0 = fexps17(acc_s[ni][0]);
            float e1 = fexps17(acc_s[ni][1]);
            float e2 = fexps17(acc_s[ni][2]);
            float e3 = fexps17(acc_s[ni][3]);
            p0 += e0 + e1;
            p1 += e2 + e3;
            int cw = (wn*32 + 8*ni + 2*qid) >> 1;
            __half2 h01 = __floats2half2_rn(e0, e1);
            __half2 h23 = __floats2half2_rn(e2, e3);
            Ps[r0*32 + (cw ^ ((r0 & 7) << 2))] = *(uint32_t*)&h01;
            int r1 = r0 + 8;
            Ps[r1*32 + (cw ^ ((r1 & 7) << 2))] = *(uint32_t*)&h23;
        }
        p0 += __shfl_xor_sync(0xffffffffu, p0, 1);
        p0 += __shfl_xor_sync(0xffffffffu, p0, 2);
        p1 += __shfl_xor_sync(0xffffffffu, p1, 1);
        p1 += __shfl_xor_sync(0xffffffffu, p1, 2);
        rs0 += p0; rs1 += p1;
        __syncthreads();

        // O += P @ V
        #pragma unroll
        for (int kk = 0; kk < 4; kk++) {
            uint32_t kbyte = (uint32_t)(kk * 32);
            uint32_t aoff = (kbyte + aHalf) ^ aXor;
            uint32_t boff = (kbyte + bHalf) ^ bXor;
            uint32_t af[4], b0f[4], b1f[4];
            ldm4(af,  pBase + aTerm + aoff);
            ldm4(b0f, vBase + bTerm0 + boff);
            ldm4(b1f, vBase + bTerm1 + boff);
            mma16(acc_o[0], af, b0f);
            mma16(acc_o[1], af, b0f + 2);
            mma16(acc_o[2], af, b1f);
            mma16(acc_o[3], af, b1f + 2);
        }
    }

    if (qid == 0) {
        rssm[wn*64 + r0]     = rs0;
        rssm[wn*64 + r0 + 8] = rs1;
    }
    __syncthreads();
    float inv0 = 1.f / (rssm[r0]     + rssm[64 + r0]);
    float inv1 = 1.f / (rssm[r0 + 8] + rssm[64 + r0 + 8]);

    #pragma unroll
    for (int ni = 0; ni < 4; ni++) {
        int col = h*HD + wn*32 + 8*ni + 2*qid;
        size_t gi0 = (size_t)(q0 + r0)*DM + col;
        size_t gi1 = (size_t)(q0 + r0 + 8)*DM + col;
        float2 x0 = *(const float2*)&x[gi0];
        float2 x1 = *(const float2*)&x[gi1];
        float2 o0 = make_float2(x0.x + acc_o[ni][0]*inv0, x0.y + acc_o[ni][1]*inv0);
        float2 o1 = make_float2(x1.x + acc_o[ni][2]*inv1, x1.y + acc_o[ni][3]*inv1);
        *(float2*)&g_res[gi0] = o0;
        *(float2*)&g_res[gi1] = o1;
    }
}

// ---------------- h = silu(a) * g -> fp16 (8 halves/thread) ----------------
__global__ void silu_mul_kernel()
{
    int i = (blockIdx.x * 256 + threadIdx.x) * 8;
    uint4 av = *(uint4*)&g_a[i];
    uint4 gv = *(uint4*)&g_gv[i];
    const __half2* ah = (const __half2*)&av;
    const __half2* gh = (const __half2*)&gv;
    uint4 ov;
    __half2* oh = (__half2*)&ov;
    #pragma unroll
    for (int j = 0; j < 4; j++) {
        float2 a = __half22float2(ah[j]);
        float2 g = __half22float2(gh[j]);
        oh[j] = __floats2half2_rn(fsilu(a.x)*g.x, fsilu(a.y)*g.y);
    }
    *(uint4*)&g_h[i] = ov;
}

// ---------------- fp16 mma GEMM, ldmatrix, BM x BN tiles ----------------
// MODE 0: fc1 : A=g_xf          B=h_fc1     -> g_t(fp16) silu(acc+bias)
// MODE 1: fc2 : A=g_t           B=h_fc2     -> out       acc+bias+res+yk0+yk1
// MODE 2: up  : A=g_xf (gather) B=h_w1/h_w3 -> g_a/g_gv  acc+bias (fp16)
// MODE 3: dn  : A=g_h (compact) B=h_w2      -> g_yk(fp16) wts*(acc+bias) scatter
template<int MODE, int BM, int BN>
__global__ void __launch_bounds__(256, 2) mma_gemm(const __half* __restrict__ Bw,
                                                   const __half* __restrict__ Bw2,
                                                   float* __restrict__ Cout,
                                                   const float* __restrict__ bias,
                                                   const float* __restrict__ bias2)
{
    constexpr int KD  = (MODE==1) ? ISH : (MODE==3 ? NI : DM);
    constexpr int NC  = KD / 64;
    constexpr int NN  = (MODE==0) ? ISH : (MODE==2 ? NI : DM);
    constexpr int AW  = BM * 32;
    constexpr int BW  = BN * 32;
    constexpr int BOFF = 3 * AW;
    constexpr int WMN = (BM==128) ? 4 : 2;
    constexpr int WNN = 8 / WMN;
    constexpr int WNW = BN / WNN;
    constexpr int NIT = WNW / 8;
    constexpr int TPRA = 256 / BM;
    constexpr int NCA  = 128 / TPRA / 16;
    constexpr int TPRB = 256 / BN;
    constexpr int NCB  = 128 / TPRB / 16;

    int bx = blockIdx.x;
    int tgt = 0;
    const __half* Bsel = Bw;
    const float* bsel = bias;
    if (MODE == 2 && bx >= NI/BN) { tgt = 1; bx -= NI/BN; Bsel = Bw2; bsel = bias2; }
    int n0 = bx * BN;
    int m0 = blockIdx.y * BM;
    int M = SQ, moff = 0;

    if (MODE >= 2) {
        int e = blockIdx.z;
        int cnt = g_counts[e];
        if (m0 >= cnt) return;
        M = cnt; moff = g_offsets[e];
        Bsel += (size_t)e * NN * KD;
        bsel += (size_t)e * NN;
    }

    extern __shared__ __align__(128) uint32_t smu[];
    uint32_t smbase = smem_u32(smu);

    int tid = threadIdx.x, lane = tid & 31, wid = tid >> 5;
    int wm = wid & (WMN-1), wn = wid / WMN;
    int gid = lane >> 2, qid = lane & 3;

    int ra = tid / TPRA;
    int ab0 = (tid % TPRA) * (128 / TPRA);
    int hofa[NCA]; uint32_t sba[NCA];
    #pragma unroll
    for (int i = 0; i < NCA; i++) {
        int bo = ab0 + i*16;
        hofa[i] = bo >> 1;
        sba[i] = (uint32_t)(ra*128 + (bo ^ ((ra & 7) << 4)));
    }
    int mrow = m0 + ra; if (mrow > M - 1) mrow = M - 1;
    const __half* arow;
    if      (MODE == 2) arow = g_xf + (size_t)(g_list[moff + mrow] >> 1) * DM;
    else if (MODE == 3) arow = g_h  + (size_t)(moff + mrow) * NI;
    else if (MODE == 1) arow = g_t  + (size_t)mrow * ISH;
    else                arow = g_xf + (size_t)mrow * DM;

    int rb = tid / TPRB;
    int bb0 = (tid % TPRB) * (128 / TPRB);
    const __half* brow = Bsel + (size_t)(n0 + rb) * KD;
    int hofb[NCB]; uint32_t sbb[NCB];
    #pragma unroll
    for (int i = 0; i < NCB; i++) {
        int bo = bb0 + i*16;
        hofb[i] = bo >> 1;
        sbb[i] = (uint32_t)(rb*128 + (bo ^ ((rb & 7) << 4)));
    }

    int aRow0 = 32*wm + (lane & 15);
    uint32_t aHalf = (uint32_t)(lane >> 4) * 16u;
    uint32_t aXor  = (uint32_t)((aRow0 & 7) << 4);
    uint32_t aTerm[2];
    aTerm[0] = (uint32_t)(aRow0 * 128);
    aTerm[1] = (uint32_t)((aRow0 + 16) * 128);
    int bRow0 = WNW*wn + ((lane >> 4) << 3) + (lane & 7);
    uint32_t bHalf = (uint32_t)((lane >> 3) & 1) * 16u;
    uint32_t bXor  = (uint32_t)((bRow0 & 7) << 4);
    uint32_t bTerm[NIT/2 > 0 ? NIT/2 : 1];
    #pragma unroll
    for (int j = 0; j < NIT/2; j++) bTerm[j] = (uint32_t)((bRow0 + 16*j) * 128);

#define ISSUE_CHUNK(KC) do { \
        int _kc = (KC); \
        int _st = _kc % 3; \
        uint32_t _da = smbase + (uint32_t)(_st * AW * 4); \
        uint32_t _db = smbase + (uint32_t)((BOFF + _st * BW) * 4); \
        const __half* _as = arow + _kc*64; \
        const __half* _bs = brow + _kc*64; \
        _Pragma("unroll") \
        for (int _i = 0; _i < NCA; _i++) cpasync16(_da + sba[_i], _as + hofa[_i]); \
        _Pragma("unroll") \
        for (int _i = 0; _i < NCB; _i++) cpasync16(_db + sbb[_i], _bs + hofb[_i]); \
        CP_COMMIT(); \
    } while (0)

    ISSUE_CHUNK(0);
    ISSUE_CHUNK(1);

    float acc[2][NIT][4] = {};

    for (int kc = 0; kc < NC; kc++) {
        if (kc == NC - 1) { asm volatile("cp.async.wait_group 0;" ::: "memory"); }
        else              { asm volatile("cp.async.wait_group 1;" ::: "memory"); }
        __syncthreads();
        if (kc + 2 < NC) ISSUE_CHUNK(kc + 2);

        int st = kc % 3;
        uint32_t aBase = smbase + (uint32_t)(st * AW * 4);
        uint32_t bBase = smbase + (uint32_t)((BOFF + st * BW) * 4);
        #pragma unroll
        for (int kk = 0; kk < 4; kk++) {
            uint32_t kbyte = (uint32_t)(kk * 32);
            uint32_t aoff = (kbyte + aHalf) ^ aXor;
            uint32_t boff = (kbyte + bHalf) ^ bXor;
            uint32_t af[2][4], bf[NIT][2];
            ldm4(af[0], aBase + aTerm[0] + aoff);
            ldm4(af[1], aBase + aTerm[1] + aoff);
            #pragma unroll
            for (int j = 0; j < NIT/2; j++) {
                uint32_t r4[4];
                ldm4(r4, bBase + bTerm[j] + boff);
                bf[2*j][0]   = r4[0]; bf[2*j][1]   = r4[1];
                bf[2*j+1][0] = r4[2]; bf[2*j+1][1] = r4[3];
            }
            #pragma unroll
            for (int mi = 0; mi < 2; mi++)
                #pragma unroll
                for (int ni = 0; ni < NIT; ni++)
                    mma16(acc[mi][ni], af[mi], bf[ni]);
        }
    }
#undef ISSUE_CHUNK

    #pragma unroll
    for (int mi = 0; mi < 2; mi++) {
        #pragma unroll
        for (int half = 0; half < 2; half++) {
            int row = m0 + 32*wm + 16*mi + gid + 8*half;
            if (MODE >= 2 && row >= M) continue;
            #pragma unroll
            for (int ni = 0; ni < NIT; ni++) {
                float v0 = acc[mi][ni][2*half + 0];
                float v1 = acc[mi][ni][2*half + 1];
                int col = n0 + WNW*wn + 8*ni + 2*qid;
                float b0 = bsel[col], b1 = bsel[col + 1];
                if (MODE == 0) {
                    *(__half2*)&g_t[(size_t)row*ISH + col] =
                        __floats2half2_rn(fsilu(v0 + b0), fsilu(v1 + b1));
                } else if (MODE == 1) {
                    float2 rr = *(const float2*)&g_res[(size_t)row*DM + col];
                    float2 a0 = __half22float2(*(const __half2*)&g_yk[(size_t)(2*row)*DM + col]);
                    float2 a1 = __half22float2(*(const __half2*)&g_yk[(size_t)(2*row + 1)*DM + col]);
                    float2 o  = make_float2(v0 + b0 + rr.x + a0.x + a1.x,
                                            v1 + b1 + rr.y + a0.y + a1.y);
                    *(float2*)&Cout[(size_t)row*DM + col] = o;
                } else if (MODE == 2) {
                    __half* dst = (tgt ? g_gv : g_a) + (size_t)(moff + row)*NI + col;
                    *(__half2*)dst = __floats2half2_rn(v0 + b0, v1 + b1);
                } else {
                    int code = g_list[moff + row];
                    float w = g_wts[code];
                    *(__half2*)&g_yk[(size_t)code*DM + col] =
                        __floats2half2_rn(w*(v0 + b0), w*(v1 + b1));
                }
            }
        }
    }
}

// ---------------- launch ----------------
extern "C" void kernel_launch(void* const* d_in, const int* in_sizes, int n_in,
                              void* d_out, int out_size)
{
    const float* x       = (const float*)d_in[0];
    const float* norm1_w = (const float*)d_in[1];
    const float* norm3_w = (const float*)d_in[2];
    const float* gate_w  = (const float*)d_in[3];
    const float* w1      = (const float*)d_in[4];
    const float* b1      = (const float*)d_in[5];
    const float* w2      = (const float*)d_in[6];
    const float* b2      = (const float*)d_in[7];
    const float* w3      = (const float*)d_in[8];
    const float* b3      = (const float*)d_in[9];
    const float* fc1_w   = (const float*)d_in[10];
    const float* fc1_b   = (const float*)d_in[11];
    const float* fc2_w   = (const float*)d_in[12];
    const float* fc2_b   = (const float*)d_in[13];
    float* out = (float*)d_out;

    const int SM_128_128 = 98304;
    const int SM_64_128  = 73728;
    const int SM_64_64   = 49152;
    const int SMA        = 8192*4 + 512;

    static cudaStream_t s2 = nullptr;
    static cudaEvent_t evRoot = nullptr, evA = nullptr, evB = nullptr, evC = nullptr;
    static __half *p_w1, *p_w3, *p_w2, *p_fc1, *p_fc2;
    if (!s2) {
        cudaStreamCreateWithFlags(&s2, cudaStreamNonBlocking);
        cudaEventCreateWithFlags(&evRoot, cudaEventDisableTiming);
        cudaEventCreateWithFlags(&evA, cudaEventDisableTiming);
        cudaEventCreateWithFlags(&evB, cudaEventDisableTiming);
        cudaEventCreateWithFlags(&evC, cudaEventDisableTiming);
        cudaFuncSetAttribute((mma_gemm<0,128,128>), cudaFuncAttributeMaxDynamicSharedMemorySize, SM_128_128);
        cudaFuncSetAttribute((mma_gemm<1,64,64>),   cudaFuncAttributeMaxDynamicSharedMemorySize, SM_64_64);
        cudaFuncSetAttribute((mma_gemm<2,128,128>), cudaFuncAttributeMaxDynamicSharedMemorySize, SM_128_128);
        cudaFuncSetAttribute((mma_gemm<3,64,128>),  cudaFuncAttributeMaxDynamicSharedMemorySize, SM_64_128);
        cudaFuncSetAttribute(attn_mma_kernel,       cudaFuncAttributeMaxDynamicSharedMemorySize, SMA);
        cudaGetSymbolAddress((void**)&p_w1,  h_w1);
        cudaGetSymbolAddress((void**)&p_w3,  h_w3);
        cudaGetSymbolAddress((void**)&p_w2,  h_w2);
        cudaGetSymbolAddress((void**)&p_fc1, h_fc1);
        cudaGetSymbolAddress((void**)&p_fc2, h_fc2);
    }

    cudaEventRecord(evRoot, 0);
    cudaStreamWaitEvent(s2, evRoot, 0);
    cvt_kernel<<<(NE*NI*DM/4+255)/256, 256, 0, s2>>>((const float4*)w1,    (__half2*)p_w1,  NE*NI*DM/4);
    cvt_kernel<<<(NE*NI*DM/4+255)/256, 256, 0, s2>>>((const float4*)w3,    (__half2*)p_w3,  NE*NI*DM/4);
    cvt_kernel<<<(NE*DM*NI/4+255)/256, 256, 0, s2>>>((const float4*)w2,    (__half2*)p_w2,  NE*DM*NI/4);
    cvt_kernel<<<(ISH*DM/4+255)/256,   256, 0, s2>>>((const float4*)fc1_w, (__half2*)p_fc1, ISH*DM/4);
    cvt_kernel<<<(DM*ISH/4+255)/256,   256, 0, s2>>>((const float4*)fc2_w, (__half2*)p_fc2, DM*ISH/4);
    cudaEventRecord(evC, s2);

    rmsnorm_kernel<0><<<SQ, 256>>>(x, norm1_w, nullptr);
    attn_mma_kernel<<<dim3(SQ/64, NH), 256, SMA>>>(x);
    rmsnorm_kernel<1><<<SQ, 256>>>(nullptr, norm3_w, gate_w);

    cudaEventRecord(evA, 0);
    cudaStreamWaitEvent(s2, evA, 0);
    mma_gemm<0,128,128><<<dim3(ISH/128, SQ/128), 256, SM_128_128, s2>>>(p_fc1, nullptr, nullptr, fc1_b, nullptr);
    cudaEventRecord(evB, s2);

    route_kernel<<<1, 1024>>>();
    cudaStreamWaitEvent(0, evC, 0);
    mma_gemm<2,128,128><<<dim3(2*NI/128, 32, NE), 256, SM_128_128>>>(p_w1, p_w3, nullptr, b1, b3);
    silu_mul_kernel<<<(NSLOT*NI)/2048, 256>>>();
    mma_gemm<3,64,128><<<dim3(DM/128, NSLOT/64, NE), 256, SM_64_128>>>(p_w2, nullptr, nullptr, b2, nullptr);

    cudaStreamWaitEvent(0, evB, 0);
    mma_gemm<1,64,64><<<dim3(DM/64, SQ/64), 256, SM_64_64>>>(p_fc2, nullptr, out, fc2_b, nullptr);
}